// round 6
// baseline (speedup 1.0000x reference)
#include <cuda_runtime.h>
#include <stdint.h>

// Problem constants
#define NB 4096          // batch
#define HB 128           // hash bits
#define TD 768           // teacher dim
#define BT 128           // GEMM tile (rows = cols)
#define KC 32            // K chunk staged in smem
#define TILES (NB / BT)  // 32
#define INV_TEMP 5.0f    // 1 / 0.2

// -------------------- device scratch (no allocations allowed) --------------------
__device__ float g_LN[NB * HB];   // l2-normalized logits
__device__ float g_TN[NB * TD];   // l2-normalized teacher
__device__ float g_denom[NB];     // sum of exp(sim - 5) over off-diagonal
__device__ float g_pos[NB];       // sum of sim * mask
__device__ float g_cnt[NB];       // sum of mask
__device__ float g_scal[2];       // [0]=distill SSE (sym-weighted), [1]=quant sum

// -------------------- zero accumulators --------------------
__global__ void zero_kernel() {
  int t = blockIdx.x * blockDim.x + threadIdx.x;
  for (int i = t; i < NB; i += blockDim.x * gridDim.x) {
    g_denom[i] = 0.f;
    g_pos[i] = 0.f;
    g_cnt[i] = 0.f;
  }
  if (t < 2) g_scal[t] = 0.f;
}

// -------------------- prep: normalize logits rows + quant loss --------------------
// one warp per row of 128; lane holds 4 contiguous floats
__global__ void __launch_bounds__(256) prep_logits_kernel(const float* __restrict__ x) {
  const int row = blockIdx.x * 8 + (threadIdx.x >> 5);
  const int lane = threadIdx.x & 31;
  const float4 v = *reinterpret_cast<const float4*>(x + (size_t)row * HB + lane * 4);
  float ss = v.x * v.x + v.y * v.y + v.z * v.z + v.w * v.w;
  float q = fabsf(fabsf(v.x) - 1.f) + fabsf(fabsf(v.y) - 1.f) +
            fabsf(fabsf(v.z) - 1.f) + fabsf(fabsf(v.w) - 1.f);
#pragma unroll
  for (int o = 16; o > 0; o >>= 1) {
    ss += __shfl_xor_sync(0xffffffffu, ss, o);
    q += __shfl_xor_sync(0xffffffffu, q, o);
  }
  const float scale = 1.0f / fmaxf(sqrtf(ss), 1e-12f);
  float4 o4;
  o4.x = v.x * scale; o4.y = v.y * scale; o4.z = v.z * scale; o4.w = v.w * scale;
  *reinterpret_cast<float4*>(g_LN + (size_t)row * HB + lane * 4) = o4;
  if (lane == 0) atomicAdd(&g_scal[1], q);
}

// -------------------- prep: normalize teacher rows --------------------
// one warp per row of 768; lane holds 6 float4 (strided by 128 floats)
__global__ void __launch_bounds__(256) prep_teacher_kernel(const float* __restrict__ x) {
  const int row = blockIdx.x * 8 + (threadIdx.x >> 5);
  const int lane = threadIdx.x & 31;
  float4 v[6];
  float ss = 0.f;
#pragma unroll
  for (int s = 0; s < 6; s++) {
    v[s] = *reinterpret_cast<const float4*>(x + (size_t)row * TD + s * 128 + lane * 4);
    ss += v[s].x * v[s].x + v[s].y * v[s].y + v[s].z * v[s].z + v[s].w * v[s].w;
  }
#pragma unroll
  for (int o = 16; o > 0; o >>= 1) ss += __shfl_xor_sync(0xffffffffu, ss, o);
  const float scale = 1.0f / fmaxf(sqrtf(ss), 1e-12f);
#pragma unroll
  for (int s = 0; s < 6; s++) {
    float4 o4;
    o4.x = v[s].x * scale; o4.y = v[s].y * scale;
    o4.z = v[s].z * scale; o4.w = v[s].w * scale;
    *reinterpret_cast<float4*>(g_TN + (size_t)row * TD + s * 128 + lane * 4) = o4;
  }
}

// -------------------- shared tile loader: global [row][k] -> smem [k][row] --------------------
// 256 threads stage a 128-row x 32-k tile. Coalesced float4 global loads; the
// 4 scalar STS land in distinct-bank patterns (<=4-way), negligible vs compute.
__device__ __forceinline__ void load_tile(float S[KC][BT + 4], const float* __restrict__ X,
                                          int rowbase, int kb, int ld, int tid) {
#pragma unroll
  for (int p = 0; p < 4; p++) {
    const int r = p * 32 + (tid >> 3);
    const int kq = (tid & 7) << 2;
    const float4 v = *reinterpret_cast<const float4*>(X + (size_t)(rowbase + r) * ld + kb + kq);
    S[kq + 0][r] = v.x;
    S[kq + 1][r] = v.y;
    S[kq + 2][r] = v.z;
    S[kq + 3][r] = v.w;
  }
}

// -------------------- 8x8 micro-tile FFMA over one K chunk --------------------
// SUB=false: acc += a*b   SUB=true: acc -= a*b (single FFMA with negated src)
template <bool SUB>
__device__ __forceinline__ void mma_chunk(float acc[8][8],
                                          const float A[KC][BT + 4],
                                          const float Bs[KC][BT + 4],
                                          int tx, int ty) {
#pragma unroll 8
  for (int k = 0; k < KC; k++) {
    float a[8], b[8];
    *reinterpret_cast<float4*>(&a[0]) = *reinterpret_cast<const float4*>(&A[k][ty * 8]);
    *reinterpret_cast<float4*>(&a[4]) = *reinterpret_cast<const float4*>(&A[k][ty * 8 + 4]);
    *reinterpret_cast<float4*>(&b[0]) = *reinterpret_cast<const float4*>(&Bs[k][tx * 8]);
    *reinterpret_cast<float4*>(&b[4]) = *reinterpret_cast<const float4*>(&Bs[k][tx * 8 + 4]);
#pragma unroll
    for (int m = 0; m < 8; m++)
#pragma unroll
      for (int n = 0; n < 8; n++)
        acc[m][n] = SUB ? fmaf(-a[m], b[n], acc[m][n]) : fmaf(a[m], b[n], acc[m][n]);
  }
}

// -------------------- contrastive: sim tile + fused LSE/pos/cnt epilogue --------------------
// Full 32x32 tile grid. |sim| <= 5 so exp(sim - 5) is a safe fixed-shift LSE.
__global__ void __launch_bounds__(256) cont_kernel(const uint8_t* __restrict__ mraw) {
  __shared__ union {
    struct { float A[KC][BT + 4]; float B[KC][BT + 4]; } t;
    uint8_t mk[BT * BT];
  } sm;
  const int tid = threadIdx.x;
  const int tx = tid & 15, ty = tid >> 4;
  const int ti = blockIdx.x / TILES, tj = blockIdx.x % TILES;
  const int rbase = ti * BT, cbase = tj * BT;

  float acc[8][8];
#pragma unroll
  for (int m = 0; m < 8; m++)
#pragma unroll
    for (int n = 0; n < 8; n++) acc[m][n] = 0.f;

  for (int kb = 0; kb < HB; kb += KC) {
    load_tile(sm.t.A, g_LN, rbase, kb, HB, tid);
    load_tile(sm.t.B, g_LN, cbase, kb, HB, tid);
    __syncthreads();
    mma_chunk<false>(acc, sm.t.A, sm.t.B, tx, ty);
    __syncthreads();  // also protects the union overwrite below
  }

  // ---- stage the mask tile into smem (dtype-robust) ----
  // Probe: diagonal entries are guaranteed true (eye | rand).
  //   byte 4097  = element (1,1) if 1-byte bool -> nonzero only for u8 layout
  //   otherwise elements are 4-byte (int32 or float32): nonzero test on 32-bit words
  const bool is_u8 = (mraw[4097] != 0);
  if (is_u8) {
#pragma unroll
    for (int p = 0; p < 4; p++) {
      const int idx = tid + p * 256;
      const int row = idx >> 3, q = idx & 7;
      const uint4 v = *reinterpret_cast<const uint4*>(
          mraw + (size_t)(rbase + row) * NB + cbase + q * 16);
      *reinterpret_cast<uint4*>(&sm.mk[row * BT + q * 16]) = v;
    }
  } else {
    const uint32_t* m32 = reinterpret_cast<const uint32_t*>(mraw);
#pragma unroll
    for (int p = 0; p < 16; p++) {
      const int idx = tid + p * 256;
      const int row = idx >> 5, q = idx & 31;
      const uint4 v = *reinterpret_cast<const uint4*>(
          m32 + (size_t)(rbase + row) * NB + cbase + q * 4);
      uint8_t* d = &sm.mk[row * BT + q * 4];
      d[0] = (v.x != 0u); d[1] = (v.y != 0u); d[2] = (v.z != 0u); d[3] = (v.w != 0u);
    }
  }
  __syncthreads();

  // ---- epilogue: per-row exp-sum (off-diag), masked pos-sum, count ----
#pragma unroll
  for (int m = 0; m < 8; m++) {
    const int gi = rbase + ty * 8 + m;
    float dsum = 0.f, psum = 0.f, csum = 0.f;
#pragma unroll
    for (int n = 0; n < 8; n++) {
      const int gj = cbase + tx * 8 + n;
      const float s = acc[m][n] * INV_TEMP;
      if (gi != gj) dsum += __expf(s - INV_TEMP);
      if (sm.mk[(ty * 8 + m) * BT + tx * 8 + n]) { psum += s; csum += 1.f; }
    }
#pragma unroll
    for (int o = 8; o > 0; o >>= 1) {
      dsum += __shfl_down_sync(0xffffffffu, dsum, o, 16);
      psum += __shfl_down_sync(0xffffffffu, psum, o, 16);
      csum += __shfl_down_sync(0xffffffffu, csum, o, 16);
    }
    if (tx == 0) {
      atomicAdd(&g_denom[gi], dsum);
      atomicAdd(&g_pos[gi], psum);
      atomicAdd(&g_cnt[gi], csum);
    }
  }
}

// -------------------- distillation: upper-triangle tile pairs --------------------
// acc := hash_sim (K=128, scaled 1/128), then acc -= teacher products (K=768),
// leaving acc = hash_sim - teacher_sim. Off-diagonal tiles weighted 2x (symmetry).
__global__ void __launch_bounds__(256) distill_kernel(const float* __restrict__ hash) {
  __shared__ float SA[KC][BT + 4];
  __shared__ float SB[KC][BT + 4];
  const int tid = threadIdx.x;
  const int tx = tid & 15, ty = tid >> 4;

  int p = blockIdx.x, ti = 0;
  while (p >= TILES - ti) { p -= TILES - ti; ti++; }
  const int tj = ti + p;
  const int rbase = ti * BT, cbase = tj * BT;
  const float wgt = (ti == tj) ? 1.f : 2.f;

  float acc[8][8];
#pragma unroll
  for (int m = 0; m < 8; m++)
#pragma unroll
    for (int n = 0; n < 8; n++) acc[m][n] = 0.f;

  // hash similarity (exact integers in fp32)
  for (int kb = 0; kb < HB; kb += KC) {
    load_tile(SA, hash, rbase, kb, HB, tid);
    load_tile(SB, hash, cbase, kb, HB, tid);
    __syncthreads();
    mma_chunk<false>(acc, SA, SB, tx, ty);
    __syncthreads();
  }
#pragma unroll
  for (int m = 0; m < 8; m++)
#pragma unroll
    for (int n = 0; n < 8; n++) acc[m][n] *= (1.0f / HB);

  // subtract teacher similarity
  for (int kb = 0; kb < TD; kb += KC) {
    load_tile(SA, g_TN, rbase, kb, TD, tid);
    load_tile(SB, g_TN, cbase, kb, TD, tid);
    __syncthreads();
    mma_chunk<true>(acc, SA, SB, tx, ty);
    __syncthreads();
  }

  float local = 0.f;
#pragma unroll
  for (int m = 0; m < 8; m++)
#pragma unroll
    for (int n = 0; n < 8; n++) local += acc[m][n] * acc[m][n];
  local *= wgt;

#pragma unroll
  for (int o = 16; o > 0; o >>= 1) local += __shfl_down_sync(0xffffffffu, local, o);
  __shared__ float red[8];
  if ((tid & 31) == 0) red[tid >> 5] = local;
  __syncthreads();
  if (tid < 8) {
    float v = red[tid];
#pragma unroll
    for (int o = 4; o > 0; o >>= 1) v += __shfl_down_sync(0x000000ffu, v, o);
    if (tid == 0) atomicAdd(&g_scal[0], v);
  }
}

// -------------------- finalize: combine the three losses --------------------
__global__ void finalize_kernel(float* __restrict__ out) {
  __shared__ double red[256];
  double s = 0.0;
  for (int r = threadIdx.x; r < NB; r += 256) {
    const float c = fmaxf(g_cnt[r], 1.f);
    // log_denom = 5 + log(sum exp(s-5));  per_row = -pos_mean + log_denom
    s += (double)(INV_TEMP + logf(g_denom[r]) - g_pos[r] / c);
  }
  red[threadIdx.x] = s;
  __syncthreads();
  for (int o = 128; o > 0; o >>= 1) {
    if (threadIdx.x < o) red[threadIdx.x] += red[threadIdx.x + o];
    __syncthreads();
  }
  if (threadIdx.x == 0) {
    const double cont = red[0] / (double)NB;
    const double dist = (double)g_scal[0] / ((double)NB * (double)NB);
    const double quant = (double)g_scal[1] / ((double)NB * (double)HB);
    out[0] = (float)(cont + 0.5 * dist + 0.01 * quant);
  }
}

// -------------------- launch --------------------
extern "C" void kernel_launch(void* const* d_in, const int* in_sizes, int n_in,
                              void* d_out, int out_size) {
  const float* logits = (const float*)d_in[0];
  const float* hash = (const float*)d_in[1];
  const float* teacher = (const float*)d_in[2];
  const uint8_t* mask = (const uint8_t*)d_in[3];
  float* out = (float*)d_out;
  (void)in_sizes; (void)n_in; (void)out_size;

  zero_kernel<<<16, 256>>>();
  prep_logits_kernel<<<NB / 8, 256>>>(logits);
  prep_teacher_kernel<<<NB / 8, 256>>>(teacher);
  cont_kernel<<<TILES * TILES, 256>>>(mask);
  distill_kernel<<<TILES * (TILES + 1) / 2, 256>>>(hash);
  finalize_kernel<<<1, 256>>>(out);
}

// round 9
// speedup vs baseline: 4.1221x; 4.1221x over previous
#include <cuda_runtime.h>
#include <cuda_bf16.h>
#include <stdint.h>

// ---------------- problem constants ----------------
#define NB 4096
#define HB 128
#define TD 768
#define TILES 32
#define KCH 64                           // bf16 K per smem chunk (128B rows, SW128)
#define INV_TEMP 5.0f
#define HASH_SCALE 0.08838834764831845f  // 1/sqrt(128)

// ---------------- device scratch ----------------
__device__ __nv_bfloat16 g_LNh[NB * HB];  // normalized logits (bf16)
__device__ __nv_bfloat16 g_Hs[NB * HB];   // hash * 1/sqrt(128) (bf16)
__device__ __nv_bfloat16 g_TNh[NB * TD];  // normalized teacher
__device__ __nv_bfloat16 g_TNn[NB * TD];  // negated normalized teacher
__device__ float g_denom[NB], g_pos[NB], g_cnt[NB], g_scal[2];

// ---------------- helpers ----------------
__device__ __forceinline__ uint32_t smem_u32(const void* p) {
  uint32_t a;
  asm("{ .reg .u64 t; cvta.to.shared.u64 t, %1; cvt.u32.u64 %0, t; }" : "=r"(a) : "l"(p));
  return a;
}

__device__ __forceinline__ void ldsm4(uint32_t* r, uint32_t addr) {
  asm volatile("ldmatrix.sync.aligned.m8n8.x4.shared.b16 {%0,%1,%2,%3}, [%4];"
               : "=r"(r[0]), "=r"(r[1]), "=r"(r[2]), "=r"(r[3]) : "r"(addr));
}

__device__ __forceinline__ void mma16816(float* c, const uint32_t* a, const uint32_t* b) {
  asm volatile(
      "mma.sync.aligned.m16n8k16.row.col.f32.bf16.bf16.f32 "
      "{%0,%1,%2,%3}, {%4,%5,%6,%7}, {%8,%9}, {%0,%1,%2,%3};"
      : "+f"(c[0]), "+f"(c[1]), "+f"(c[2]), "+f"(c[3])
      : "r"(a[0]), "r"(a[1]), "r"(a[2]), "r"(a[3]), "r"(b[0]), "r"(b[1]));
}

// ---------------- zero accumulators ----------------
__global__ void zero_kernel() {
  int t = blockIdx.x * blockDim.x + threadIdx.x;
  for (int i = t; i < NB; i += blockDim.x * gridDim.x) {
    g_denom[i] = 0.f; g_pos[i] = 0.f; g_cnt[i] = 0.f;
  }
  if (t < 2) g_scal[t] = 0.f;
}

// ---------------- prep: logits normalize + quant, hash scale ----------------
__global__ void __launch_bounds__(256) prep128_kernel(const float* __restrict__ logits,
                                                      const float* __restrict__ hash) {
  const int row = blockIdx.x * 8 + (threadIdx.x >> 5);
  const int lane = threadIdx.x & 31;
  const float4 v = *reinterpret_cast<const float4*>(logits + (size_t)row * HB + lane * 4);
  float ss = v.x * v.x + v.y * v.y + v.z * v.z + v.w * v.w;
  float q = fabsf(fabsf(v.x) - 1.f) + fabsf(fabsf(v.y) - 1.f) +
            fabsf(fabsf(v.z) - 1.f) + fabsf(fabsf(v.w) - 1.f);
#pragma unroll
  for (int o = 16; o > 0; o >>= 1) {
    ss += __shfl_xor_sync(0xffffffffu, ss, o);
    q += __shfl_xor_sync(0xffffffffu, q, o);
  }
  const float sc = 1.0f / fmaxf(sqrtf(ss), 1e-12f);
  __nv_bfloat162* lo = reinterpret_cast<__nv_bfloat162*>(g_LNh + (size_t)row * HB + lane * 4);
  lo[0] = __floats2bfloat162_rn(v.x * sc, v.y * sc);
  lo[1] = __floats2bfloat162_rn(v.z * sc, v.w * sc);
  if (lane == 0) atomicAdd(&g_scal[1], q);
  const float4 h = *reinterpret_cast<const float4*>(hash + (size_t)row * HB + lane * 4);
  __nv_bfloat162* ho = reinterpret_cast<__nv_bfloat162*>(g_Hs + (size_t)row * HB + lane * 4);
  ho[0] = __floats2bfloat162_rn(h.x * HASH_SCALE, h.y * HASH_SCALE);
  ho[1] = __floats2bfloat162_rn(h.z * HASH_SCALE, h.w * HASH_SCALE);
}

// ---------------- prep: teacher normalize (+ and -) ----------------
__global__ void __launch_bounds__(256) prep_teacher_kernel(const float* __restrict__ x) {
  const int row = blockIdx.x * 8 + (threadIdx.x >> 5);
  const int lane = threadIdx.x & 31;
  float4 v[6];
  float ss = 0.f;
#pragma unroll
  for (int s = 0; s < 6; s++) {
    v[s] = *reinterpret_cast<const float4*>(x + (size_t)row * TD + s * 128 + lane * 4);
    ss += v[s].x * v[s].x + v[s].y * v[s].y + v[s].z * v[s].z + v[s].w * v[s].w;
  }
#pragma unroll
  for (int o = 16; o > 0; o >>= 1) ss += __shfl_xor_sync(0xffffffffu, ss, o);
  const float sc = 1.0f / fmaxf(sqrtf(ss), 1e-12f);
#pragma unroll
  for (int s = 0; s < 6; s++) {
    const size_t idx = (size_t)row * TD + s * 128 + lane * 4;
    __nv_bfloat162* tp = reinterpret_cast<__nv_bfloat162*>(g_TNh + idx);
    __nv_bfloat162* tn = reinterpret_cast<__nv_bfloat162*>(g_TNn + idx);
    tp[0] = __floats2bfloat162_rn(v[s].x * sc, v[s].y * sc);
    tp[1] = __floats2bfloat162_rn(v[s].z * sc, v[s].w * sc);
    tn[0] = __floats2bfloat162_rn(-v[s].x * sc, -v[s].y * sc);
    tn[1] = __floats2bfloat162_rn(-v[s].z * sc, -v[s].w * sc);
  }
}

// ---------------- chunk source selection ----------------
template <bool DISTILL>
__device__ __forceinline__ void chunk_src(int c, const __nv_bfloat16*& A,
                                          const __nv_bfloat16*& B, int& ld, int& kb) {
  if (!DISTILL) { A = g_LNh; B = g_LNh; ld = HB; kb = c * KCH; }
  else if (c < 2) { A = g_Hs; B = g_Hs; ld = HB; kb = c * KCH; }
  else { A = g_TNh; B = g_TNn; ld = TD; kb = (c - 2) * KCH; }
}

// ---------------- stage one 128x64(bf16) A/B chunk pair via cp.async ----------------
__device__ __forceinline__ void cp_chunk(uint32_t sA, uint32_t sB,
                                         const __nv_bfloat16* __restrict__ A, int lda,
                                         const __nv_bfloat16* __restrict__ Bp, int ldb,
                                         int rbase, int cbase, int kb, int tid) {
#pragma unroll
  for (int p = 0; p < 4; p++) {
    const int lin = p * 256 + tid;  // 0..1023 x 16B segments
    const int row = lin >> 3, seg = lin & 7;
    const uint32_t off = (uint32_t)(row * 128 + seg * 16);
    const uint32_t swz = off ^ ((off >> 3) & 0x70);
    const unsigned long long ga =
        (unsigned long long)__cvta_generic_to_global(A + (size_t)(rbase + row) * lda + kb + seg * 8);
    const unsigned long long gb =
        (unsigned long long)__cvta_generic_to_global(Bp + (size_t)(cbase + row) * ldb + kb + seg * 8);
    asm volatile("cp.async.cg.shared.global [%0], [%1], 16;\n" ::"r"(sA + swz), "l"(ga));
    asm volatile("cp.async.cg.shared.global [%0], [%1], 16;\n" ::"r"(sB + swz), "l"(gb));
  }
  asm volatile("cp.async.commit_group;\n" ::: "memory");
}

// ---------------- double-buffered HMMA mainloop ----------------
// acc[mt][nt][4]: m16n8 fragment accumulators. Warp grid 2(m) x 4(n): warp tile 64x32.
template <bool DISTILL>
__device__ __forceinline__ void mma_mainloop(float acc[4][4][4], int rbase, int cbase,
                                             int tid, uint32_t sbase) {
  const int NC = DISTILL ? (HB + TD) / KCH : HB / KCH;  // 14 or 2
  const int lane = tid & 31, wid = tid >> 5;
  const int wm = (wid >> 2) * 64, wn = (wid & 3) * 32;

  // ldmatrix lane addressing (SW128: column XOR mask = (row&7)<<4, col-independent)
  const int arow = wm + (lane & 15);
  const uint32_t aX = (uint32_t)(arow & 7) << 4;
  const uint32_t aSub = (uint32_t)((lane >> 4) * 16);
  const uint32_t aRow = (uint32_t)arow * 128u;
  const int brow = wn + (lane & 7) + ((lane >> 4) & 1) * 8;
  const uint32_t bX = (uint32_t)(brow & 7) << 4;
  const uint32_t bSub = (uint32_t)(((lane >> 3) & 1) * 16);
  const uint32_t bRow = (uint32_t)brow * 128u;

  {  // prefetch chunks 0,1
    const __nv_bfloat16 *A, *B; int ld, kb;
    chunk_src<DISTILL>(0, A, B, ld, kb);
    cp_chunk(sbase, sbase + 16384u, A, ld, B, ld, rbase, cbase, kb, tid);
    chunk_src<DISTILL>(1, A, B, ld, kb);
    cp_chunk(sbase + 32768u, sbase + 49152u, A, ld, B, ld, rbase, cbase, kb, tid);
  }

  for (int c = 0; c < NC; c++) {
    const int b = c & 1;
    const uint32_t sAb = sbase + (uint32_t)b * 32768u;
    const uint32_t sBb = sAb + 16384u;
    if (c == NC - 1) asm volatile("cp.async.wait_group 0;\n" ::: "memory");
    else             asm volatile("cp.async.wait_group 1;\n" ::: "memory");
    __syncthreads();

    const uint32_t aRB = sAb + aRow;
    const uint32_t bRB = sBb + bRow;
#pragma unroll
    for (int ks = 0; ks < 4; ks++) {
      const uint32_t acol = ((uint32_t)(ks * 32) + aSub) ^ aX;
      const uint32_t bcol = ((uint32_t)(ks * 32) + bSub) ^ bX;
      uint32_t af[4][4], bf0[4], bf1[4];
#pragma unroll
      for (int mt = 0; mt < 4; mt++) ldsm4(af[mt], aRB + mt * 2048u + acol);
      ldsm4(bf0, bRB + bcol);           // n-tiles 0,1
      ldsm4(bf1, bRB + 2048u + bcol);   // n-tiles 2,3
#pragma unroll
      for (int mt = 0; mt < 4; mt++) {
        mma16816(acc[mt][0], af[mt], &bf0[0]);
        mma16816(acc[mt][1], af[mt], &bf0[2]);
        mma16816(acc[mt][2], af[mt], &bf1[0]);
        mma16816(acc[mt][3], af[mt], &bf1[2]);
      }
    }
    __syncthreads();  // everyone done reading buffer b before refill
    if (c + 2 < NC) {
      const __nv_bfloat16 *A, *B; int ld, kb;
      chunk_src<DISTILL>(c + 2, A, B, ld, kb);
      cp_chunk(sAb, sBb, A, ld, B, ld, rbase, cbase, kb, tid);
    }
  }
}

// ---------------- contrastive: GEMM + fused LSE/pos/cnt epilogue ----------------
__global__ void __launch_bounds__(256, 1) cont_mma_kernel(const uint8_t* __restrict__ mraw) {
  extern __shared__ char dsm[];
  char* dal = (char*)(((uintptr_t)dsm + 1023) & ~(uintptr_t)1023);
  const uint32_t sbase = smem_u32(dal);
  __shared__ float s_d[128], s_p[128], s_c[128];
  const int tid = threadIdx.x;
  if (tid < 128) { s_d[tid] = 0.f; s_p[tid] = 0.f; s_c[tid] = 0.f; }

  const int ti = blockIdx.x >> 5, tj = blockIdx.x & 31;
  const int rbase = ti * 128, cbase = tj * 128;

  float acc[4][4][4];
#pragma unroll
  for (int m = 0; m < 4; m++)
#pragma unroll
    for (int n = 0; n < 4; n++)
#pragma unroll
      for (int r = 0; r < 4; r++) acc[m][n][r] = 0.f;

  mma_mainloop<false>(acc, rbase, cbase, tid, sbase);

  // ---- stage mask tile into smem (reuse buffer 0; dtype-robust probe) ----
  __syncthreads();
  uint8_t* mk = (uint8_t*)dal;
  const bool is_u8 = (mraw[4097] != 0);  // (1,1) diagonal true iff 1-byte layout
  if (is_u8) {
#pragma unroll
    for (int p = 0; p < 4; p++) {
      const int idx = tid + p * 256;
      const int row = idx >> 3, q = idx & 7;
      const uint4 v = *reinterpret_cast<const uint4*>(
          mraw + (size_t)(rbase + row) * NB + cbase + q * 16);
      *reinterpret_cast<uint4*>(&mk[row * 128 + q * 16]) = v;
    }
  } else {
    const uint32_t* m32 = reinterpret_cast<const uint32_t*>(mraw);
#pragma unroll
    for (int p = 0; p < 16; p++) {
      const int idx = tid + p * 256;
      const int row = idx >> 5, q = idx & 31;
      const uint4 v = *reinterpret_cast<const uint4*>(
          m32 + (size_t)(rbase + row) * NB + cbase + q * 4);
      uint8_t* d = &mk[row * 128 + q * 4];
      d[0] = (v.x != 0u); d[1] = (v.y != 0u); d[2] = (v.z != 0u); d[3] = (v.w != 0u);
    }
  }
  __syncthreads();

  // ---- epilogue ----
  const int lane = tid & 31, wid = tid >> 5;
  const int wm = (wid >> 2) * 64, wn = (wid & 3) * 32;
#pragma unroll
  for (int mt = 0; mt < 4; mt++) {
#pragma unroll
    for (int half = 0; half < 2; half++) {
      const int rl = wm + mt * 16 + (lane >> 2) + half * 8;
      const int gi = rbase + rl;
      float dsum = 0.f, psum = 0.f, csum = 0.f;
#pragma unroll
      for (int nt = 0; nt < 4; nt++) {
#pragma unroll
        for (int e = 0; e < 2; e++) {
          const int cl = wn + nt * 8 + (lane & 3) * 2 + e;
          const float s = acc[mt][nt][half * 2 + e] * INV_TEMP;
          if (gi != cbase + cl) dsum += __expf(s - INV_TEMP);
          if (mk[rl * 128 + cl]) { psum += s; csum += 1.f; }
        }
      }
      dsum += __shfl_down_sync(0xffffffffu, dsum, 2, 4);
      dsum += __shfl_down_sync(0xffffffffu, dsum, 1, 4);
      psum += __shfl_down_sync(0xffffffffu, psum, 2, 4);
      psum += __shfl_down_sync(0xffffffffu, psum, 1, 4);
      csum += __shfl_down_sync(0xffffffffu, csum, 2, 4);
      csum += __shfl_down_sync(0xffffffffu, csum, 1, 4);
      if ((lane & 3) == 0) {
        atomicAdd(&s_d[rl], dsum);
        atomicAdd(&s_p[rl], psum);
        atomicAdd(&s_c[rl], csum);
      }
    }
  }
  __syncthreads();
  if (tid < 128) {
    atomicAdd(&g_denom[rbase + tid], s_d[tid]);
    atomicAdd(&g_pos[rbase + tid], s_p[tid]);
    atomicAdd(&g_cnt[rbase + tid], s_c[tid]);
  }
}

// ---------------- distillation: upper-triangle tiles, square-sum epilogue ----------------
__global__ void __launch_bounds__(256, 1) distill_mma_kernel() {
  extern __shared__ char dsm[];
  char* dal = (char*)(((uintptr_t)dsm + 1023) & ~(uintptr_t)1023);
  const uint32_t sbase = smem_u32(dal);
  const int tid = threadIdx.x;

  int p = blockIdx.x, ti = 0;
  while (p >= TILES - ti) { p -= TILES - ti; ti++; }
  const int tj = ti + p;
  const int rbase = ti * 128, cbase = tj * 128;
  const float wgt = (ti == tj) ? 1.f : 2.f;

  float acc[4][4][4];
#pragma unroll
  for (int m = 0; m < 4; m++)
#pragma unroll
    for (int n = 0; n < 4; n++)
#pragma unroll
      for (int r = 0; r < 4; r++) acc[m][n][r] = 0.f;

  // acc := hash_sim/128 (K=128, pre-scaled), then -= teacher_sim (K=768, negated B)
  mma_mainloop<true>(acc, rbase, cbase, tid, sbase);

  float ss = 0.f;
#pragma unroll
  for (int m = 0; m < 4; m++)
#pragma unroll
    for (int n = 0; n < 4; n++)
#pragma unroll
      for (int r = 0; r < 4; r++) ss = fmaf(acc[m][n][r], acc[m][n][r], ss);

#pragma unroll
  for (int o = 16; o > 0; o >>= 1) ss += __shfl_down_sync(0xffffffffu, ss, o);
  __shared__ float red[8];
  if ((tid & 31) == 0) red[tid >> 5] = ss;
  __syncthreads();
  if (tid < 8) {
    float v = red[tid];
#pragma unroll
    for (int o = 4; o > 0; o >>= 1) v += __shfl_down_sync(0x000000ffu, v, o);
    if (tid == 0) atomicAdd(&g_scal[0], v * wgt);
  }
}

// ---------------- finalize ----------------
__global__ void finalize_kernel(float* __restrict__ out) {
  __shared__ double red[256];
  double s = 0.0;
  for (int r = threadIdx.x; r < NB; r += 256) {
    const float c = fmaxf(g_cnt[r], 1.f);
    s += (double)(INV_TEMP + logf(g_denom[r]) - g_pos[r] / c);
  }
  red[threadIdx.x] = s;
  __syncthreads();
  for (int o = 128; o > 0; o >>= 1) {
    if (threadIdx.x < o) red[threadIdx.x] += red[threadIdx.x + o];
    __syncthreads();
  }
  if (threadIdx.x == 0) {
    const double cont = red[0] / (double)NB;
    const double dist = (double)g_scal[0] / ((double)NB * (double)NB);
    const double quant = (double)g_scal[1] / ((double)NB * (double)HB);
    out[0] = (float)(cont + 0.5 * dist + 0.01 * quant);
  }
}

// ---------------- launch ----------------
extern "C" void kernel_launch(void* const* d_in, const int* in_sizes, int n_in,
                              void* d_out, int out_size) {
  const float* logits = (const float*)d_in[0];
  const float* hash = (const float*)d_in[1];
  const float* teacher = (const float*)d_in[2];
  const uint8_t* mask = (const uint8_t*)d_in[3];
  float* out = (float*)d_out;
  (void)in_sizes; (void)n_in; (void)out_size;

  const int DSM = 64 * 1024 + 1024;  // 2 x (16K A + 16K B) + alignment slack
  static bool attr_done = false;
  if (!attr_done) {
    cudaFuncSetAttribute(cont_mma_kernel, cudaFuncAttributeMaxDynamicSharedMemorySize, DSM);
    cudaFuncSetAttribute(distill_mma_kernel, cudaFuncAttributeMaxDynamicSharedMemorySize, DSM);
    attr_done = true;
  }

  zero_kernel<<<16, 256>>>();
  prep128_kernel<<<NB / 8, 256>>>(logits, hash);
  prep_teacher_kernel<<<NB / 8, 256>>>(teacher);
  cont_mma_kernel<<<TILES * TILES, 256, DSM>>>(mask);
  distill_mma_kernel<<<TILES * (TILES + 1) / 2, 256, DSM>>>();
  finalize_kernel<<<1, 256>>>(out);
}

// round 10
// speedup vs baseline: 5.5863x; 1.3552x over previous
#include <cuda_runtime.h>
#include <cuda_bf16.h>
#include <stdint.h>

// ---------------- problem constants ----------------
#define NB 4096
#define HB 128
#define TD 768
#define TILES 32
#define KCH 64                           // bf16 K per smem chunk (128B rows, SW128)
#define INV_TEMP 5.0f
#define HASH_SCALE 0.08838834764831845f  // 1/sqrt(128)
#define CONT_BLOCKS (TILES * TILES)                  // 1024
#define DIST_BLOCKS (TILES * (TILES + 1) / 2)        // 528

// ---------------- device scratch ----------------
__device__ __nv_bfloat16 g_LNh[NB * HB];  // normalized logits (bf16)
__device__ __nv_bfloat16 g_Hs[NB * HB];   // hash * 1/sqrt(128) (bf16)
__device__ __nv_bfloat16 g_TNh[NB * TD];  // normalized teacher
__device__ __nv_bfloat16 g_TNn[NB * TD];  // negated normalized teacher
__device__ float g_denom[NB], g_pos[NB], g_cnt[NB];
__device__ float g_distill;               // distill SSE (zeroed in prep)
__device__ float g_qpart[NB / 8];         // per-block quant partials (plain stores)

// ---------------- helpers ----------------
__device__ __forceinline__ uint32_t smem_u32(const void* p) {
  uint32_t a;
  asm("{ .reg .u64 t; cvta.to.shared.u64 t, %1; cvt.u32.u64 %0, t; }" : "=r"(a) : "l"(p));
  return a;
}

__device__ __forceinline__ void ldsm4(uint32_t* r, uint32_t addr) {
  asm volatile("ldmatrix.sync.aligned.m8n8.x4.shared.b16 {%0,%1,%2,%3}, [%4];"
               : "=r"(r[0]), "=r"(r[1]), "=r"(r[2]), "=r"(r[3]) : "r"(addr));
}

__device__ __forceinline__ void mma16816(float* c, const uint32_t* a, const uint32_t* b) {
  asm volatile(
      "mma.sync.aligned.m16n8k16.row.col.f32.bf16.bf16.f32 "
      "{%0,%1,%2,%3}, {%4,%5,%6,%7}, {%8,%9}, {%0,%1,%2,%3};"
      : "+f"(c[0]), "+f"(c[1]), "+f"(c[2]), "+f"(c[3])
      : "r"(a[0]), "r"(a[1]), "r"(a[2]), "r"(a[3]), "r"(b[0]), "r"(b[1]));
}

// ---------------- fused prep: zero accs + normalize logits/teacher + scale hash ----------------
// grid = NB/8 = 512 blocks, 256 threads. Warp w handles row = bid*8 + w.
__global__ void __launch_bounds__(256) prep_kernel(const float* __restrict__ logits,
                                                   const float* __restrict__ hash,
                                                   const float* __restrict__ teacher) {
  const int tid = threadIdx.x;
  // zero accumulators (first 16 blocks cover NB; launch boundary orders vs pair_kernel)
  {
    const int idx = blockIdx.x * 256 + tid;
    if (idx < NB) { g_denom[idx] = 0.f; g_pos[idx] = 0.f; g_cnt[idx] = 0.f; }
    if (idx == 0) g_distill = 0.f;
  }
  const int row = blockIdx.x * 8 + (tid >> 5);
  const int lane = tid & 31;

  // ---- logits: normalize + quant partial ----
  const float4 v = *reinterpret_cast<const float4*>(logits + (size_t)row * HB + lane * 4);
  float ss = v.x * v.x + v.y * v.y + v.z * v.z + v.w * v.w;
  float q = fabsf(fabsf(v.x) - 1.f) + fabsf(fabsf(v.y) - 1.f) +
            fabsf(fabsf(v.z) - 1.f) + fabsf(fabsf(v.w) - 1.f);
#pragma unroll
  for (int o = 16; o > 0; o >>= 1) {
    ss += __shfl_xor_sync(0xffffffffu, ss, o);
    q += __shfl_xor_sync(0xffffffffu, q, o);
  }
  const float sc = 1.0f / fmaxf(sqrtf(ss), 1e-12f);
  __nv_bfloat162* lo = reinterpret_cast<__nv_bfloat162*>(g_LNh + (size_t)row * HB + lane * 4);
  lo[0] = __floats2bfloat162_rn(v.x * sc, v.y * sc);
  lo[1] = __floats2bfloat162_rn(v.z * sc, v.w * sc);

  // block-reduce quant partial -> plain store (no pre-zero needed)
  __shared__ float s_q[8];
  if (lane == 0) s_q[tid >> 5] = q;
  __syncthreads();
  if (tid == 0) {
    float t = 0.f;
#pragma unroll
    for (int w = 0; w < 8; w++) t += s_q[w];
    g_qpart[blockIdx.x] = t;
  }

  // ---- hash: scale by 1/sqrt(128) ----
  const float4 h = *reinterpret_cast<const float4*>(hash + (size_t)row * HB + lane * 4);
  __nv_bfloat162* ho = reinterpret_cast<__nv_bfloat162*>(g_Hs + (size_t)row * HB + lane * 4);
  ho[0] = __floats2bfloat162_rn(h.x * HASH_SCALE, h.y * HASH_SCALE);
  ho[1] = __floats2bfloat162_rn(h.z * HASH_SCALE, h.w * HASH_SCALE);

  // ---- teacher: normalize (+ and -) ----
  float4 tv[6];
  float ts = 0.f;
#pragma unroll
  for (int s = 0; s < 6; s++) {
    tv[s] = *reinterpret_cast<const float4*>(teacher + (size_t)row * TD + s * 128 + lane * 4);
    ts += tv[s].x * tv[s].x + tv[s].y * tv[s].y + tv[s].z * tv[s].z + tv[s].w * tv[s].w;
  }
#pragma unroll
  for (int o = 16; o > 0; o >>= 1) ts += __shfl_xor_sync(0xffffffffu, ts, o);
  const float tsc = 1.0f / fmaxf(sqrtf(ts), 1e-12f);
#pragma unroll
  for (int s = 0; s < 6; s++) {
    const size_t idx = (size_t)row * TD + s * 128 + lane * 4;
    __nv_bfloat162* tp = reinterpret_cast<__nv_bfloat162*>(g_TNh + idx);
    __nv_bfloat162* tn = reinterpret_cast<__nv_bfloat162*>(g_TNn + idx);
    tp[0] = __floats2bfloat162_rn(tv[s].x * tsc, tv[s].y * tsc);
    tp[1] = __floats2bfloat162_rn(tv[s].z * tsc, tv[s].w * tsc);
    tn[0] = __floats2bfloat162_rn(-tv[s].x * tsc, -tv[s].y * tsc);
    tn[1] = __floats2bfloat162_rn(-tv[s].z * tsc, -tv[s].w * tsc);
  }
}

// ---------------- chunk source selection ----------------
template <bool DISTILL>
__device__ __forceinline__ void chunk_src(int c, const __nv_bfloat16*& A,
                                          const __nv_bfloat16*& B, int& ld, int& kb) {
  if (!DISTILL) { A = g_LNh; B = g_LNh; ld = HB; kb = c * KCH; }
  else if (c < 2) { A = g_Hs; B = g_Hs; ld = HB; kb = c * KCH; }
  else { A = g_TNh; B = g_TNn; ld = TD; kb = (c - 2) * KCH; }
}

// ---------------- stage one 128x64(bf16) A/B chunk pair via cp.async ----------------
__device__ __forceinline__ void cp_chunk(uint32_t sA, uint32_t sB,
                                         const __nv_bfloat16* __restrict__ A, int lda,
                                         const __nv_bfloat16* __restrict__ Bp, int ldb,
                                         int rbase, int cbase, int kb, int tid) {
#pragma unroll
  for (int p = 0; p < 4; p++) {
    const int lin = p * 256 + tid;  // 0..1023 x 16B segments
    const int row = lin >> 3, seg = lin & 7;
    const uint32_t off = (uint32_t)(row * 128 + seg * 16);
    const uint32_t swz = off ^ ((off >> 3) & 0x70);
    const unsigned long long ga =
        (unsigned long long)__cvta_generic_to_global(A + (size_t)(rbase + row) * lda + kb + seg * 8);
    const unsigned long long gb =
        (unsigned long long)__cvta_generic_to_global(Bp + (size_t)(cbase + row) * ldb + kb + seg * 8);
    asm volatile("cp.async.cg.shared.global [%0], [%1], 16;\n" ::"r"(sA + swz), "l"(ga));
    asm volatile("cp.async.cg.shared.global [%0], [%1], 16;\n" ::"r"(sB + swz), "l"(gb));
  }
  asm volatile("cp.async.commit_group;\n" ::: "memory");
}

// ---------------- double-buffered HMMA mainloop (warp tile 64x32) ----------------
template <bool DISTILL>
__device__ __forceinline__ void mma_mainloop(float acc[4][4][4], int rbase, int cbase,
                                             int tid, uint32_t sbase) {
  const int NC = DISTILL ? (HB + TD) / KCH : HB / KCH;  // 14 or 2
  const int lane = tid & 31, wid = tid >> 5;
  const int wm = (wid >> 2) * 64, wn = (wid & 3) * 32;

  // ldmatrix lane addressing (SW128: XOR mask = (row&7)<<4, column-independent)
  const int arow = wm + (lane & 15);
  const uint32_t aX = (uint32_t)(arow & 7) << 4;
  const uint32_t aSub = (uint32_t)((lane >> 4) * 16);
  const uint32_t aRow = (uint32_t)arow * 128u;
  const int brow = wn + (lane & 7) + ((lane >> 4) & 1) * 8;
  const uint32_t bX = (uint32_t)(brow & 7) << 4;
  const uint32_t bSub = (uint32_t)(((lane >> 3) & 1) * 16);
  const uint32_t bRow = (uint32_t)brow * 128u;

  {  // prefetch chunks 0,1
    const __nv_bfloat16 *A, *B; int ld, kb;
    chunk_src<DISTILL>(0, A, B, ld, kb);
    cp_chunk(sbase, sbase + 16384u, A, ld, B, ld, rbase, cbase, kb, tid);
    chunk_src<DISTILL>(1, A, B, ld, kb);
    cp_chunk(sbase + 32768u, sbase + 49152u, A, ld, B, ld, rbase, cbase, kb, tid);
  }

  for (int c = 0; c < NC; c++) {
    const int b = c & 1;
    const uint32_t sAb = sbase + (uint32_t)b * 32768u;
    const uint32_t sBb = sAb + 16384u;
    if (c == NC - 1) asm volatile("cp.async.wait_group 0;\n" ::: "memory");
    else             asm volatile("cp.async.wait_group 1;\n" ::: "memory");
    __syncthreads();

    const uint32_t aRB = sAb + aRow;
    const uint32_t bRB = sBb + bRow;
#pragma unroll
    for (int ks = 0; ks < 4; ks++) {
      const uint32_t acol = ((uint32_t)(ks * 32) + aSub) ^ aX;
      const uint32_t bcol = ((uint32_t)(ks * 32) + bSub) ^ bX;
      uint32_t af[4][4], bf0[4], bf1[4];
#pragma unroll
      for (int mt = 0; mt < 4; mt++) ldsm4(af[mt], aRB + mt * 2048u + acol);
      ldsm4(bf0, bRB + bcol);           // n-tiles 0,1
      ldsm4(bf1, bRB + 2048u + bcol);   // n-tiles 2,3
#pragma unroll
      for (int mt = 0; mt < 4; mt++) {
        mma16816(acc[mt][0], af[mt], &bf0[0]);
        mma16816(acc[mt][1], af[mt], &bf0[2]);
        mma16816(acc[mt][2], af[mt], &bf1[0]);
        mma16816(acc[mt][3], af[mt], &bf1[2]);
      }
    }
    __syncthreads();  // all reads of buffer b done before refill
    if (c + 2 < NC) {
      const __nv_bfloat16 *A, *B; int ld, kb;
      chunk_src<DISTILL>(c + 2, A, B, ld, kb);
      cp_chunk(sAb, sBb, A, ld, B, ld, rbase, cbase, kb, tid);
    }
  }
}

// ---------------- fused pair kernel: cont tiles [0,1024) + distill triangle [1024,1552) ----
__global__ void __launch_bounds__(256, 2) pair_kernel(const uint8_t* __restrict__ mraw) {
  extern __shared__ char dsm[];
  char* dal = (char*)(((uintptr_t)dsm + 1023) & ~(uintptr_t)1023);
  const uint32_t sbase = smem_u32(dal);
  const int tid = threadIdx.x;

  float acc[4][4][4];
#pragma unroll
  for (int m = 0; m < 4; m++)
#pragma unroll
    for (int n = 0; n < 4; n++)
#pragma unroll
      for (int r = 0; r < 4; r++) acc[m][n][r] = 0.f;

  if (blockIdx.x < CONT_BLOCKS) {
    // ================= contrastive =================
    __shared__ float s_d[128], s_p[128], s_c[128];
    if (tid < 128) { s_d[tid] = 0.f; s_p[tid] = 0.f; s_c[tid] = 0.f; }
    const int ti = blockIdx.x >> 5, tj = blockIdx.x & 31;
    const int rbase = ti * 128, cbase = tj * 128;

    mma_mainloop<false>(acc, rbase, cbase, tid, sbase);

    // stage mask tile into smem (reuse buffer; dtype-robust probe)
    __syncthreads();
    uint8_t* mk = (uint8_t*)dal;
    const bool is_u8 = (mraw[4097] != 0);  // (1,1) diagonal true iff 1-byte layout
    if (is_u8) {
#pragma unroll
      for (int p = 0; p < 4; p++) {
        const int idx = tid + p * 256;
        const int row = idx >> 3, q = idx & 7;
        const uint4 v = *reinterpret_cast<const uint4*>(
            mraw + (size_t)(rbase + row) * NB + cbase + q * 16);
        *reinterpret_cast<uint4*>(&mk[row * 128 + q * 16]) = v;
      }
    } else {
      const uint32_t* m32 = reinterpret_cast<const uint32_t*>(mraw);
#pragma unroll
      for (int p = 0; p < 16; p++) {
        const int idx = tid + p * 256;
        const int row = idx >> 5, q = idx & 31;
        const uint4 v = *reinterpret_cast<const uint4*>(
            m32 + (size_t)(rbase + row) * NB + cbase + q * 4);
        uint8_t* d = &mk[row * 128 + q * 4];
        d[0] = (v.x != 0u); d[1] = (v.y != 0u); d[2] = (v.z != 0u); d[3] = (v.w != 0u);
      }
    }
    __syncthreads();

    const int lane = tid & 31, wid = tid >> 5;
    const int wm = (wid >> 2) * 64, wn = (wid & 3) * 32;
#pragma unroll
    for (int mt = 0; mt < 4; mt++) {
#pragma unroll
      for (int half = 0; half < 2; half++) {
        const int rl = wm + mt * 16 + (lane >> 2) + half * 8;
        const int gi = rbase + rl;
        float dsum = 0.f, psum = 0.f, csum = 0.f;
#pragma unroll
        for (int nt = 0; nt < 4; nt++) {
#pragma unroll
          for (int e = 0; e < 2; e++) {
            const int cl = wn + nt * 8 + (lane & 3) * 2 + e;
            const float s = acc[mt][nt][half * 2 + e] * INV_TEMP;
            if (gi != cbase + cl) dsum += __expf(s - INV_TEMP);
            if (mk[rl * 128 + cl]) { psum += s; csum += 1.f; }
          }
        }
        dsum += __shfl_down_sync(0xffffffffu, dsum, 2, 4);
        dsum += __shfl_down_sync(0xffffffffu, dsum, 1, 4);
        psum += __shfl_down_sync(0xffffffffu, psum, 2, 4);
        psum += __shfl_down_sync(0xffffffffu, psum, 1, 4);
        csum += __shfl_down_sync(0xffffffffu, csum, 2, 4);
        csum += __shfl_down_sync(0xffffffffu, csum, 1, 4);
        if ((lane & 3) == 0) {
          atomicAdd(&s_d[rl], dsum);
          atomicAdd(&s_p[rl], psum);
          atomicAdd(&s_c[rl], csum);
        }
      }
    }
    __syncthreads();
    if (tid < 128) {
      atomicAdd(&g_denom[rbase + tid], s_d[tid]);
      atomicAdd(&g_pos[rbase + tid], s_p[tid]);
      atomicAdd(&g_cnt[rbase + tid], s_c[tid]);
    }
  } else {
    // ================= distillation (upper triangle) =================
    int p = blockIdx.x - CONT_BLOCKS, ti = 0;
    while (p >= TILES - ti) { p -= TILES - ti; ti++; }
    const int tj = ti + p;
    const int rbase = ti * 128, cbase = tj * 128;
    const float wgt = (ti == tj) ? 1.f : 2.f;

    // acc := hash_sim/128 (K=128, pre-scaled), then -= teacher_sim (K=768, negated B)
    mma_mainloop<true>(acc, rbase, cbase, tid, sbase);

    float ss = 0.f;
#pragma unroll
    for (int m = 0; m < 4; m++)
#pragma unroll
      for (int n = 0; n < 4; n++)
#pragma unroll
        for (int r = 0; r < 4; r++) ss = fmaf(acc[m][n][r], acc[m][n][r], ss);

#pragma unroll
    for (int o = 16; o > 0; o >>= 1) ss += __shfl_down_sync(0xffffffffu, ss, o);
    __shared__ float red[8];
    if ((tid & 31) == 0) red[tid >> 5] = ss;
    __syncthreads();
    if (tid < 8) {
      float v = red[tid];
#pragma unroll
      for (int o = 4; o > 0; o >>= 1) v += __shfl_down_sync(0x000000ffu, v, o);
      if (tid == 0) atomicAdd(&g_distill, v * wgt);
    }
  }
}

// ---------------- finalize ----------------
__global__ void finalize_kernel(float* __restrict__ out) {
  __shared__ double red[256];
  double s = 0.0;
  for (int r = threadIdx.x; r < NB; r += 256) {
    const float c = fmaxf(g_cnt[r], 1.f);
    s += (double)(INV_TEMP + logf(g_denom[r]) - g_pos[r] / c);
  }
  // quant partials
  float q = 0.f;
  for (int r = threadIdx.x; r < NB / 8; r += 256) q += g_qpart[r];
  red[threadIdx.x] = s + 0.0;  // keep cont sum in double
  __shared__ float redq[256];
  redq[threadIdx.x] = q;
  __syncthreads();
  for (int o = 128; o > 0; o >>= 1) {
    if (threadIdx.x < o) {
      red[threadIdx.x] += red[threadIdx.x + o];
      redq[threadIdx.x] += redq[threadIdx.x + o];
    }
    __syncthreads();
  }
  if (threadIdx.x == 0) {
    const double cont = red[0] / (double)NB;
    const double dist = (double)g_distill / ((double)NB * (double)NB);
    const double quant = (double)redq[0] / ((double)NB * (double)HB);
    out[0] = (float)(cont + 0.5 * dist + 0.01 * quant);
  }
}

// ---------------- launch ----------------
extern "C" void kernel_launch(void* const* d_in, const int* in_sizes, int n_in,
                              void* d_out, int out_size) {
  const float* logits = (const float*)d_in[0];
  const float* hash = (const float*)d_in[1];
  const float* teacher = (const float*)d_in[2];
  const uint8_t* mask = (const uint8_t*)d_in[3];
  float* out = (float*)d_out;
  (void)in_sizes; (void)n_in; (void)out_size;

  const int DSM = 64 * 1024 + 1024;  // 2 x (16K A + 16K B) + alignment slack
  cudaFuncSetAttribute(pair_kernel, cudaFuncAttributeMaxDynamicSharedMemorySize, DSM);

  prep_kernel<<<NB / 8, 256>>>(logits, hash, teacher);
  pair_kernel<<<CONT_BLOCKS + DIST_BLOCKS, 256, DSM>>>(mask);
  finalize_kernel<<<1, 256>>>(out);
}